// round 3
// baseline (speedup 1.0000x reference)
#include <cuda_runtime.h>
#include <cuda_bf16.h>

// ---------------------------------------------------------------------------
// NeuralMapCell pipeline, fp32.
// Output: concat( c_t[256], r_t[256], new_mem[256*4096] )
// ---------------------------------------------------------------------------

#define H 64
#define W 64
#define UNITS 256
#define C1OC 32
#define C2OC 64
#define H2 62
#define HP 61
#define FLAT (64*61*61)   // 238144
#define NPIX 4096
#define D1BLK 296
#define D1ROWS 805        // ceil(FLAT / D1BLK)
#define CTBLK 128

// Scratch
__device__ float g_c1[H*W*C1OC];
__device__ float g_c2[C2OC*H2*H2];
__device__ float g_flat[FLAT];
__device__ float g_part1[D1BLK*128];
__device__ float g_qpre[4*256];
__device__ float g_spre[4*256];
__device__ float g_rt[256];
__device__ float g_qt[256];
__device__ float g_st[256];
__device__ float g_scores[NPIX];
__device__ float g_expv[NPIX];
__device__ float g_invsum;
__device__ float g_partC[CTBLK*256];

// ---------------------------------------------------------------------------
// pre: input-only projections, k-split over 4 blocks.
// ---------------------------------------------------------------------------
__global__ __launch_bounds__(256) void pre_kernel(
    const float* __restrict__ inputs, const float* __restrict__ ctx,
    const float* __restrict__ rec)
{
    const int c = threadIdx.x;
    const int k0 = blockIdx.x * 32;
    float q = 0.f, s = 0.f;
    #pragma unroll 8
    for (int k = 0; k < 32; k++) {
        float iv = __ldg(inputs + k0 + k);
        q += iv * __ldg(ctx + (k0 + k)*256 + c);
        s += iv * __ldg(rec + (k0 + k)*256 + c);
    }
    g_qpre[blockIdx.x*256 + c] = q;
    g_spre[blockIdx.x*256 + c] = s;
}

// ---------------------------------------------------------------------------
// conv1: SAME 3x3, 256 -> 32 ch. Tile = 4 rows x 8 cols, grid (8,16)=128.
// Per ic-quad: 4 LDG.128 weights (coalesced over o4) + 1 broadcast LDS.128
// activation + 16 FFMA.
// ---------------------------------------------------------------------------
__global__ __launch_bounds__(256) void conv1_kernel(
    const float* __restrict__ mem, const float* __restrict__ w1)
{
    extern __shared__ float sin1[];        // 60 px (6 rows x 10 cols) x 256 ch
    const int bw = blockIdx.x * 8;
    const int bh = blockIdx.y * 4;
    const int t = threadIdx.x;

    for (int idx = t; idx < 60*64; idx += 256) {
        int p = idx >> 6;
        int q = idx & 63;
        int r = p / 10, c = p % 10;
        int h = bh + r - 1, w = bw + c - 1;
        float4 v = make_float4(0.f,0.f,0.f,0.f);
        if (h >= 0 && h < H && w >= 0 && w < W)
            v = reinterpret_cast<const float4*>(mem + (h*W + w)*UNITS)[q];
        reinterpret_cast<float4*>(sin1 + p*256)[q] = v;
    }
    __syncthreads();

    const int lane = t & 31;
    const int wid  = t >> 5;
    const int o4   = lane & 7;
    const int px   = lane >> 3;
    const int row  = wid & 3;
    const int col  = (wid >> 2)*4 + px;

    float4 acc = make_float4(0.f,0.f,0.f,0.f);

    #pragma unroll
    for (int kh = 0; kh < 3; kh++) {
        #pragma unroll
        for (int kw = 0; kw < 3; kw++) {
            const float* __restrict__ wp = w1 + ((kh*3 + kw)*256)*32 + o4*4;
            const float* __restrict__ ap = sin1 + ((row+kh)*10 + (col+kw))*256;
            #pragma unroll 2
            for (int ic4 = 0; ic4 < 64; ic4++) {
                float4 a  = reinterpret_cast<const float4*>(ap)[ic4];
                float4 w0 = __ldg(reinterpret_cast<const float4*>(wp + (4*ic4+0)*32));
                float4 wa = __ldg(reinterpret_cast<const float4*>(wp + (4*ic4+1)*32));
                float4 wb = __ldg(reinterpret_cast<const float4*>(wp + (4*ic4+2)*32));
                float4 wc = __ldg(reinterpret_cast<const float4*>(wp + (4*ic4+3)*32));
                acc.x += a.x*w0.x + a.y*wa.x + a.z*wb.x + a.w*wc.x;
                acc.y += a.x*w0.y + a.y*wa.y + a.z*wb.y + a.w*wc.y;
                acc.z += a.x*w0.z + a.y*wa.z + a.z*wb.z + a.w*wc.z;
                acc.w += a.x*w0.w + a.y*wa.w + a.z*wb.w + a.w*wc.w;
            }
        }
    }
    reinterpret_cast<float4*>(g_c1 + ((bh+row)*W + (bw+col))*C1OC)[o4] = acc;
}

// ---------------------------------------------------------------------------
// conv2: VALID 3x3, 32 -> 64 ch, output 62x62. Tile 2 rows x 8 cols, grid (8,31).
// ---------------------------------------------------------------------------
__global__ __launch_bounds__(256) void conv2_kernel(
    const float* __restrict__ w2)
{
    __shared__ float s2[40*32];            // 4 rows x 10 cols halo
    const int bw = blockIdx.x * 8;
    const int bh = blockIdx.y * 2;
    const int t = threadIdx.x;

    for (int idx = t; idx < 40*8; idx += 256) {
        int p = idx >> 3;
        int q = idx & 7;
        int r = p / 10, c = p % 10;
        int h = bh + r, w = bw + c;
        float4 v = make_float4(0.f,0.f,0.f,0.f);
        if (h < H && w < W)
            v = reinterpret_cast<const float4*>(g_c1 + (h*W + w)*C1OC)[q];
        reinterpret_cast<float4*>(s2 + p*32)[q] = v;
    }
    __syncthreads();

    const int lane = t & 31;
    const int wid  = t >> 5;
    const int o4   = lane & 15;
    const int px   = lane >> 4;
    const int row  = wid & 1;
    const int col  = (wid >> 1)*2 + px;

    float4 acc = make_float4(0.f,0.f,0.f,0.f);

    #pragma unroll
    for (int kh = 0; kh < 3; kh++) {
        #pragma unroll
        for (int kw = 0; kw < 3; kw++) {
            const float* __restrict__ wp = w2 + ((kh*3 + kw)*32)*64 + o4*4;
            const float* __restrict__ ap = s2 + ((row+kh)*10 + (col+kw))*32;
            #pragma unroll
            for (int ic4 = 0; ic4 < 8; ic4++) {
                float4 a  = reinterpret_cast<const float4*>(ap)[ic4];
                float4 w0 = __ldg(reinterpret_cast<const float4*>(wp + (4*ic4+0)*64));
                float4 wa = __ldg(reinterpret_cast<const float4*>(wp + (4*ic4+1)*64));
                float4 wb = __ldg(reinterpret_cast<const float4*>(wp + (4*ic4+2)*64));
                float4 wc = __ldg(reinterpret_cast<const float4*>(wp + (4*ic4+3)*64));
                acc.x += a.x*w0.x + a.y*wa.x + a.z*wb.x + a.w*wc.x;
                acc.y += a.x*w0.y + a.y*wa.y + a.z*wb.y + a.w*wc.y;
                acc.z += a.x*w0.z + a.y*wa.z + a.z*wb.z + a.w*wc.z;
                acc.w += a.x*w0.w + a.y*wa.w + a.z*wb.w + a.w*wc.w;
            }
        }
    }
    const int h2 = bh + row;
    const int w2i = bw + col;
    if (w2i < H2) {
        g_c2[(4*o4+0)*(H2*H2) + h2*H2 + w2i] = acc.x;
        g_c2[(4*o4+1)*(H2*H2) + h2*H2 + w2i] = acc.y;
        g_c2[(4*o4+2)*(H2*H2) + h2*H2 + w2i] = acc.z;
        g_c2[(4*o4+3)*(H2*H2) + h2*H2 + w2i] = acc.w;
    }
}

// ---------------------------------------------------------------------------
// pool: 2x2 sum pool (stride 1) * 0.25 -> flat
// ---------------------------------------------------------------------------
__global__ __launch_bounds__(256) void pool_kernel()
{
    int idx = blockIdx.x * 256 + threadIdx.x;
    if (idx >= FLAT) return;
    int oc = idx / (HP*HP);
    int r = idx - oc*(HP*HP);
    int h = r / HP;
    int w = r - h*HP;
    const float* base = g_c2 + oc*(H2*H2) + h*H2 + w;
    g_flat[idx] = 0.25f * (base[0] + base[1] + base[H2] + base[H2+1]);
}

// ---------------------------------------------------------------------------
// dense1: float4 per-lane loads, 4-row unroll for MLP.
// ---------------------------------------------------------------------------
__global__ __launch_bounds__(256) void dense1_kernel(const float* __restrict__ W1)
{
    const int t = threadIdx.x;
    const int lane = t & 31;
    const int wid  = t >> 5;
    const int row0 = blockIdx.x * D1ROWS;
    int lim = row0 + D1ROWS;
    if (lim > FLAT) lim = FLAT;

    float4 acc = make_float4(0.f,0.f,0.f,0.f);
    for (int k = 0; k < 104; k += 4) {          // 104*8 = 832 >= 805 rows
        #pragma unroll
        for (int u = 0; u < 4; u++) {
            int i = row0 + wid + 8*(k + u);
            if (i < lim) {
                float f = __ldg(g_flat + i);
                float4 wv = __ldg(reinterpret_cast<const float4*>(W1 + (size_t)i*128) + lane);
                acc.x += f*wv.x; acc.y += f*wv.y; acc.z += f*wv.z; acc.w += f*wv.w;
            }
        }
    }
    __shared__ float4 sred[256];
    sred[wid*32 + lane] = acc;
    __syncthreads();
    if (t < 32) {
        float4 s = sred[t];
        #pragma unroll
        for (int w = 1; w < 8; w++) {
            float4 v = sred[w*32 + t];
            s.x += v.x; s.y += v.y; s.z += v.z; s.w += v.w;
        }
        reinterpret_cast<float4*>(g_part1 + blockIdx.x*128)[t] = s;
    }
}

// ---------------------------------------------------------------------------
// fuse1 (1 block, 1024 threads): reduce part1 -> r128; rt = r128@W2 (k-split 4);
// q = qpre + rt@ctx[128:]; s = spre.
// ---------------------------------------------------------------------------
__global__ __launch_bounds__(1024) void fuse1_kernel(
    const float* __restrict__ W2, const float* __restrict__ ctx)
{
    __shared__ float s_r128[128];
    __shared__ float s_rt[256];
    __shared__ float s_part[4*256];
    __shared__ float s_tmp[512];
    const int t = threadIdx.x;
    const int c = t & 255;
    const int seg = t >> 8;

    if (t < 512) {
        int col = t & 127;
        int half = t >> 7;
        float a = 0.f;
        #pragma unroll 8
        for (int b = half*148; b < half*148 + 148; b++)
            a += g_part1[b*128 + col];
        s_tmp[t] = a;
    }
    __syncthreads();
    if (t < 128) s_r128[t] = s_tmp[t] + s_tmp[t + 128];
    __syncthreads();

    {
        float p = 0.f;
        #pragma unroll 8
        for (int k = 0; k < 32; k++) {
            int kk = seg*32 + k;
            p += s_r128[kk] * __ldg(W2 + kk*256 + c);
        }
        s_part[seg*256 + c] = p;
    }
    __syncthreads();
    if (t < 256) {
        float rt = s_part[t] + s_part[256 + t] + s_part[512 + t] + s_part[768 + t];
        s_rt[t] = rt;
        g_rt[t] = rt;
    }
    __syncthreads();

    {
        float q = 0.f;
        #pragma unroll 8
        for (int k = 0; k < 64; k++) {
            int kk = seg*64 + k;
            q += s_rt[kk] * __ldg(ctx + (128 + kk)*256 + c);
        }
        s_part[seg*256 + c] = q;
    }
    __syncthreads();
    if (t < 256) {
        float q = s_part[t] + s_part[256 + t] + s_part[512 + t] + s_part[768 + t]
                + g_qpre[t] + g_qpre[256 + t] + g_qpre[512 + t] + g_qpre[768 + t];
        g_qt[t] = q;
        g_st[t] = g_spre[t] + g_spre[256 + t] + g_spre[512 + t] + g_spre[768 + t];
    }
}

// ---------------------------------------------------------------------------
// scores[p] = dot(q_t, memory[p,:]) — warp per row
// ---------------------------------------------------------------------------
__global__ __launch_bounds__(256) void scores_kernel(const float* __restrict__ mem)
{
    __shared__ float4 sq[64];
    const int t = threadIdx.x;
    if (t < 64) sq[t] = reinterpret_cast<const float4*>(g_qt)[t];
    __syncthreads();

    const int lane = t & 31;
    const int p = blockIdx.x * 8 + (t >> 5);
    const float4* mp = reinterpret_cast<const float4*>(mem + p*UNITS);
    float4 m0 = mp[lane];
    float4 m1 = mp[lane + 32];
    float4 q0 = sq[lane];
    float4 q1 = sq[lane + 32];
    float acc = m0.x*q0.x + m0.y*q0.y + m0.z*q0.z + m0.w*q0.w
              + m1.x*q1.x + m1.y*q1.y + m1.z*q1.z + m1.w*q1.w;
    #pragma unroll
    for (int o = 16; o > 0; o >>= 1)
        acc += __shfl_down_sync(0xffffffffu, acc, o);
    if (lane == 0) g_scores[p] = acc;
}

// ---------------------------------------------------------------------------
// softmax over 4096 scores
// ---------------------------------------------------------------------------
__global__ __launch_bounds__(1024) void softmax_kernel()
{
    __shared__ float red[32];
    const int t = threadIdx.x;
    float4 v = reinterpret_cast<const float4*>(g_scores)[t];
    float m = fmaxf(fmaxf(v.x, v.y), fmaxf(v.z, v.w));
    #pragma unroll
    for (int o = 16; o > 0; o >>= 1)
        m = fmaxf(m, __shfl_xor_sync(0xffffffffu, m, o));
    if ((t & 31) == 0) red[t >> 5] = m;
    __syncthreads();
    if (t < 32) {
        float mm = red[t];
        #pragma unroll
        for (int o = 16; o > 0; o >>= 1)
            mm = fmaxf(mm, __shfl_xor_sync(0xffffffffu, mm, o));
        red[t] = mm;
    }
    __syncthreads();
    const float gmax = red[0];
    __syncthreads();

    float4 e;
    e.x = expf(v.x - gmax); e.y = expf(v.y - gmax);
    e.z = expf(v.z - gmax); e.w = expf(v.w - gmax);
    reinterpret_cast<float4*>(g_expv)[t] = e;
    float s = e.x + e.y + e.z + e.w;
    #pragma unroll
    for (int o = 16; o > 0; o >>= 1)
        s += __shfl_xor_sync(0xffffffffu, s, o);
    if ((t & 31) == 0) red[t >> 5] = s;
    __syncthreads();
    if (t == 0) {
        float ss = 0.f;
        for (int i = 0; i < 32; i++) ss += red[i];
        g_invsum = 1.f / ss;
    }
}

// ---------------------------------------------------------------------------
// c_t partials: 128 blocks x 32 rows
// ---------------------------------------------------------------------------
__global__ __launch_bounds__(256) void ctpart_kernel(const float* __restrict__ mem)
{
    const int c = threadIdx.x;
    const int base = blockIdx.x * 32;
    float acc = 0.f;
    #pragma unroll 8
    for (int p = base; p < base + 32; p++)
        acc += g_expv[p] * __ldg(mem + p*UNITS + c);
    g_partC[blockIdx.x*256 + c] = acc;
}

// ---------------------------------------------------------------------------
// Transpose memory (4096,256) -> new_mem region of out
// ---------------------------------------------------------------------------
__global__ __launch_bounds__(256) void transpose_kernel(
    const float* __restrict__ mem, float* __restrict__ out)
{
    __shared__ float tile[32][33];
    const int p0 = blockIdx.x * 32;
    const int c0 = blockIdx.y * 32;
    const int tx = threadIdx.x, ty = threadIdx.y;
    #pragma unroll
    for (int j = ty; j < 32; j += 8)
        tile[j][tx] = mem[(p0 + j)*UNITS + c0 + tx];
    __syncthreads();
    #pragma unroll
    for (int j = ty; j < 32; j += 8)
        out[512 + (size_t)(c0 + j)*NPIX + p0 + tx] = tile[tx][j];
}

// ---------------------------------------------------------------------------
// Final: reduce c_t, importances, mem update at (x,y)
// ---------------------------------------------------------------------------
__global__ __launch_bounds__(256) void final_kernel(
    const float* __restrict__ mem, const float* __restrict__ rec,
    const int* __restrict__ px, const int* __restrict__ py,
    float* __restrict__ out)
{
    __shared__ float s_st[256], s_mold[256];
    __shared__ float red[16];
    __shared__ float s_frac;
    const int c = threadIdx.x;
    const int pos = px[0]*W + py[0];

    float ct = 0.f;
    #pragma unroll 8
    for (int b = 0; b < CTBLK; b++) ct += g_partC[b*256 + c];
    ct *= g_invsum;
    float rt = g_rt[c];
    float st = g_st[c];
    s_st[c] = st;
    s_mold[c] = mem[pos*UNITS + c];
    out[c] = ct;
    out[256 + c] = rt;

    float li = st * ct;
    float gi = st * rt;
    #pragma unroll
    for (int o = 16; o > 0; o >>= 1) {
        li += __shfl_xor_sync(0xffffffffu, li, o);
        gi += __shfl_xor_sync(0xffffffffu, gi, o);
    }
    if ((c & 31) == 0) {
        red[c >> 5] = li;
        red[8 + (c >> 5)] = gi;
    }
    __syncthreads();
    if (c == 0) {
        float L = 0.f, G = 0.f;
        for (int i = 0; i < 8; i++) { L += red[i]; G += red[8 + i]; }
        s_frac = L / (L + G);
    }
    __syncthreads();

    const float frac = s_frac;
    float d = 0.f;
    #pragma unroll 8
    for (int k = 0; k < 256; k++)
        d += (s_mold[k] - s_st[k]) * __ldg(rec + (128 + k)*256 + c);
    out[512 + (size_t)c*NPIX + pos] = s_mold[c] + frac * d;
}

// ---------------------------------------------------------------------------
extern "C" void kernel_launch(void* const* d_in, const int* in_sizes, int n_in,
                              void* d_out, int out_size)
{
    const float* inputs = (const float*)d_in[0];
    const float* mem    = (const float*)d_in[1];
    const float* ck1    = (const float*)d_in[2];
    const float* ck2    = (const float*)d_in[3];
    const float* cd1    = (const float*)d_in[4];
    const float* cd2    = (const float*)d_in[5];
    const float* ctx    = (const float*)d_in[6];
    const float* rec    = (const float*)d_in[7];
    const int*   px     = (const int*)d_in[8];
    const int*   py     = (const int*)d_in[9];
    float* out = (float*)d_out;

    cudaFuncSetAttribute(conv1_kernel,
                         cudaFuncAttributeMaxDynamicSharedMemorySize,
                         60*256*4);

    pre_kernel<<<4, 256>>>(inputs, ctx, rec);
    conv1_kernel<<<dim3(8, 16), 256, 60*256*4>>>(mem, ck1);
    conv2_kernel<<<dim3(8, 31), 256>>>(ck2);
    pool_kernel<<<(FLAT + 255) / 256, 256>>>();
    dense1_kernel<<<D1BLK, 256>>>(cd1);
    fuse1_kernel<<<1, 1024>>>(cd2, ctx);
    scores_kernel<<<NPIX / 8, 256>>>(mem);
    softmax_kernel<<<1, 1024>>>();
    ctpart_kernel<<<CTBLK, 256>>>(mem);
    transpose_kernel<<<dim3(NPIX / 32, UNITS / 32), dim3(32, 8)>>>(mem, out);
    final_kernel<<<1, 256>>>(mem, rec, px, py, out);
}

// round 4
// speedup vs baseline: 1.5114x; 1.5114x over previous
#include <cuda_runtime.h>
#include <cuda_bf16.h>

// ---------------------------------------------------------------------------
// NeuralMapCell pipeline, fp32. Round-1 structure + vectorized dense1.
// Launch order puts conv1 4th (ncu captures the 4th launch).
// Output: concat( c_t[256], r_t[256], new_mem[256*4096] )
// ---------------------------------------------------------------------------

#define H 64
#define W 64
#define UNITS 256
#define C1OC 32
#define C2OC 64
#define H2 62            // conv2 VALID output
#define HP 61            // pool output
#define FLAT (64*61*61)  // 238144
#define NPIX 4096
#define D1BLK 296
#define D1ROWS 805       // ceil(FLAT / D1BLK)
#define CTBLK 64

// Scratch (device globals; no allocation allowed)
__device__ float g_c1[H*W*C1OC];        // [h][w][oc]
__device__ float g_c2[C2OC*H2*H2];      // [oc][h2][w2]
__device__ float g_flat[FLAT];          // [oc][h][w] of pool
__device__ float g_part1[D1BLK*128];
__device__ float g_rt[256];
__device__ float g_qt[256];
__device__ float g_st[256];
__device__ float g_scores[NPIX];
__device__ float g_expv[NPIX];
__device__ float g_invsum;
__device__ float g_partC[CTBLK*256];

// ---------------------------------------------------------------------------
// conv1: SAME 3x3, 256 -> 32 channels over 64x64. (round-1 version)
// Block = 4x4 output tile, 256 threads. Input halo (6x6 px x 256ch) in smem.
// ---------------------------------------------------------------------------
__global__ __launch_bounds__(256) void conv1_kernel(
    const float* __restrict__ mem, const float* __restrict__ w1)
{
    __shared__ float sin[36*256];   // 36 KB
    const int bw = blockIdx.x * 4;
    const int bh = blockIdx.y * 4;
    const int t = threadIdx.x;

    for (int idx = t; idx < 36*64; idx += 256) {
        int p = idx >> 6;
        int q = idx & 63;
        int ph = p / 6, pw = p % 6;
        int h = bh + ph - 1, w = bw + pw - 1;
        float4 v = make_float4(0.f,0.f,0.f,0.f);
        if (h >= 0 && h < H && w >= 0 && w < W)
            v = reinterpret_cast<const float4*>(mem + (h*W + w)*UNITS)[q];
        reinterpret_cast<float4*>(sin + p*256)[q] = v;
    }
    __syncthreads();

    const int oc = t & 31;
    const int pg = t >> 5;          // 0..7, each handles 2 pixels of the 4x4 tile
    const int p0 = pg*2, p1 = pg*2 + 1;
    const int ph0 = p0 >> 2, pw0 = p0 & 3;
    const int ph1 = p1 >> 2, pw1 = p1 & 3;

    float acc0 = 0.f, acc1 = 0.f;
    #pragma unroll
    for (int kh = 0; kh < 3; kh++) {
        #pragma unroll
        for (int kw = 0; kw < 3; kw++) {
            const float* __restrict__ wp = w1 + ((kh*3 + kw)*256)*32 + oc;
            const float* __restrict__ s0 = sin + ((ph0+kh)*6 + (pw0+kw))*256;
            const float* __restrict__ s1 = sin + ((ph1+kh)*6 + (pw1+kw))*256;
            #pragma unroll 8
            for (int ic = 0; ic < 256; ic++) {
                float wv = __ldg(wp + ic*32);
                acc0 += wv * s0[ic];
                acc1 += wv * s1[ic];
            }
        }
    }
    g_c1[((bh+ph0)*W + (bw+pw0))*C1OC + oc] = acc0;
    g_c1[((bh+ph1)*W + (bw+pw1))*C1OC + oc] = acc1;
}

// ---------------------------------------------------------------------------
// conv2: VALID 3x3, 32 -> 64 channels, output 62x62. (round-1 version)
// ---------------------------------------------------------------------------
__global__ __launch_bounds__(256) void conv2_kernel(
    const float* __restrict__ w2)
{
    __shared__ float s2[60*32];     // 6x10 pixel halo
    const int bw = blockIdx.x * 8;
    const int bh = blockIdx.y * 4;
    const int t = threadIdx.x;

    for (int idx = t; idx < 60*8; idx += 256) {
        int p = idx >> 3;
        int q = idx & 7;
        int ph = p / 10, pw = p % 10;
        int h = bh + ph, w = bw + pw;
        float4 v = make_float4(0.f,0.f,0.f,0.f);
        if (h < H && w < W)
            v = reinterpret_cast<const float4*>(g_c1 + (h*W + w)*C1OC)[q];
        reinterpret_cast<float4*>(s2 + p*32)[q] = v;
    }
    __syncthreads();

    const int oc = t & 63;
    const int pg = t >> 6;
    float acc[8];
    #pragma unroll
    for (int i = 0; i < 8; i++) acc[i] = 0.f;

    #pragma unroll
    for (int kh = 0; kh < 3; kh++) {
        #pragma unroll
        for (int kw = 0; kw < 3; kw++) {
            const float* __restrict__ wp = w2 + ((kh*3 + kw)*32)*64 + oc;
            const float* __restrict__ sp = s2 + ((pg+kh)*10 + kw)*32;
            #pragma unroll 4
            for (int ic = 0; ic < 32; ic++) {
                float wv = __ldg(wp + ic*64);
                #pragma unroll
                for (int pw = 0; pw < 8; pw++)
                    acc[pw] += wv * sp[pw*32 + ic];
            }
        }
    }
    const int h2 = bh + pg;
    if (h2 < H2) {
        #pragma unroll
        for (int pw = 0; pw < 8; pw++) {
            int w2i = bw + pw;
            if (w2i < H2)
                g_c2[oc*(H2*H2) + h2*H2 + w2i] = acc[pw];
        }
    }
}

// ---------------------------------------------------------------------------
// 2x2 sum pool (stride 1) * 0.25 -> flat
// ---------------------------------------------------------------------------
__global__ __launch_bounds__(256) void pool_kernel()
{
    int idx = blockIdx.x * 256 + threadIdx.x;
    if (idx >= FLAT) return;
    int oc = idx / (HP*HP);
    int r = idx - oc*(HP*HP);
    int h = r / HP;
    int w = r - h*HP;
    const float* base = g_c2 + oc*(H2*H2) + h*H2 + w;
    g_flat[idx] = 0.25f * (base[0] + base[1] + base[H2] + base[H2+1]);
}

// ---------------------------------------------------------------------------
// dense1: flat(1x238144) @ W1(238144x128). Vectorized: per-lane float4 loads
// (512B per warp per row), 4-row unroll for MLP. 296 blocks x 8 warps.
// ---------------------------------------------------------------------------
__global__ __launch_bounds__(256) void dense1_kernel(const float* __restrict__ W1)
{
    const int t = threadIdx.x;
    const int lane = t & 31;
    const int wid  = t >> 5;
    const int row0 = blockIdx.x * D1ROWS;
    int lim = row0 + D1ROWS;
    if (lim > FLAT) lim = FLAT;

    float4 acc = make_float4(0.f,0.f,0.f,0.f);
    for (int k = 0; k < 104; k += 4) {          // 104*8 = 832 >= 805 rows
        #pragma unroll
        for (int u = 0; u < 4; u++) {
            int i = row0 + wid + 8*(k + u);
            if (i < lim) {
                float f = __ldg(g_flat + i);
                float4 wv = __ldg(reinterpret_cast<const float4*>(W1 + (size_t)i*128) + lane);
                acc.x += f*wv.x; acc.y += f*wv.y; acc.z += f*wv.z; acc.w += f*wv.w;
            }
        }
    }
    __shared__ float4 sred[256];
    sred[wid*32 + lane] = acc;
    __syncthreads();
    if (t < 32) {
        float4 s = sred[t];
        #pragma unroll
        for (int w = 1; w < 8; w++) {
            float4 v = sred[w*32 + t];
            s.x += v.x; s.y += v.y; s.z += v.z; s.w += v.w;
        }
        reinterpret_cast<float4*>(g_part1 + blockIdx.x*128)[t] = s;
    }
}

// ---------------------------------------------------------------------------
// fuse1 (round-1 version, 296 partials): reduce r128; r_t = r128@W2;
// q_t = [in,r_t]@ctx; s_t = in@rec[:128]. Single block, 256 threads.
// ---------------------------------------------------------------------------
__global__ __launch_bounds__(256) void fuse1_kernel(
    const float* __restrict__ inputs, const float* __restrict__ W2,
    const float* __restrict__ ctx, const float* __restrict__ rec)
{
    __shared__ float s_r128[128];
    __shared__ float s_rt[256];
    __shared__ float s_in[128];
    const int t = threadIdx.x;

    if (t < 128) {
        float a = 0.f;
        #pragma unroll 8
        for (int b = 0; b < D1BLK; b++) a += g_part1[b*128 + t];
        s_r128[t] = a;
        s_in[t] = inputs[t];
    }
    __syncthreads();

    float rt = 0.f;
    #pragma unroll 8
    for (int k = 0; k < 128; k++) rt += s_r128[k] * W2[k*256 + t];
    s_rt[t] = rt;
    g_rt[t] = rt;
    __syncthreads();

    float q = 0.f, sv = 0.f;
    #pragma unroll 8
    for (int k = 0; k < 128; k++) {
        float iv = s_in[k];
        q  += iv * ctx[k*256 + t];
        sv += iv * rec[k*256 + t];
    }
    #pragma unroll 8
    for (int k = 0; k < 256; k++)
        q += s_rt[k] * ctx[(128 + k)*256 + t];
    g_qt[t] = q;
    g_st[t] = sv;
}

// ---------------------------------------------------------------------------
// scores[p] = dot(q_t, memory[p,:])  — warp per row
// ---------------------------------------------------------------------------
__global__ __launch_bounds__(256) void scores_kernel(const float* __restrict__ mem)
{
    __shared__ float4 sq[64];
    const int t = threadIdx.x;
    if (t < 64) sq[t] = reinterpret_cast<const float4*>(g_qt)[t];
    __syncthreads();

    const int lane = t & 31;
    const int p = blockIdx.x * 8 + (t >> 5);
    const float4* mp = reinterpret_cast<const float4*>(mem + p*UNITS);
    float4 m0 = mp[lane];
    float4 m1 = mp[lane + 32];
    float4 q0 = sq[lane];
    float4 q1 = sq[lane + 32];
    float acc = m0.x*q0.x + m0.y*q0.y + m0.z*q0.z + m0.w*q0.w
              + m1.x*q1.x + m1.y*q1.y + m1.z*q1.z + m1.w*q1.w;
    #pragma unroll
    for (int o = 16; o > 0; o >>= 1)
        acc += __shfl_down_sync(0xffffffffu, acc, o);
    if (lane == 0) g_scores[p] = acc;
}

// ---------------------------------------------------------------------------
// softmax over 4096 scores (single block)
// ---------------------------------------------------------------------------
__global__ __launch_bounds__(1024) void softmax_kernel()
{
    __shared__ float red[32];
    const int t = threadIdx.x;
    float4 v = reinterpret_cast<const float4*>(g_scores)[t];
    float m = fmaxf(fmaxf(v.x, v.y), fmaxf(v.z, v.w));
    #pragma unroll
    for (int o = 16; o > 0; o >>= 1)
        m = fmaxf(m, __shfl_xor_sync(0xffffffffu, m, o));
    if ((t & 31) == 0) red[t >> 5] = m;
    __syncthreads();
    if (t < 32) {
        float mm = red[t];
        #pragma unroll
        for (int o = 16; o > 0; o >>= 1)
            mm = fmaxf(mm, __shfl_xor_sync(0xffffffffu, mm, o));
        red[t] = mm;
    }
    __syncthreads();
    const float gmax = red[0];
    __syncthreads();

    float4 e;
    e.x = expf(v.x - gmax); e.y = expf(v.y - gmax);
    e.z = expf(v.z - gmax); e.w = expf(v.w - gmax);
    reinterpret_cast<float4*>(g_expv)[t] = e;
    float s = e.x + e.y + e.z + e.w;
    #pragma unroll
    for (int o = 16; o > 0; o >>= 1)
        s += __shfl_xor_sync(0xffffffffu, s, o);
    if ((t & 31) == 0) red[t >> 5] = s;
    __syncthreads();
    if (t == 0) {
        float ss = 0.f;
        for (int i = 0; i < 32; i++) ss += red[i];
        g_invsum = 1.f / ss;
    }
}

// ---------------------------------------------------------------------------
// c_t partials: sum_p expv[p] * memory[p,:], 64 blocks of 64 rows
// ---------------------------------------------------------------------------
__global__ __launch_bounds__(256) void ctpart_kernel(const float* __restrict__ mem)
{
    const int c = threadIdx.x;
    const int base = blockIdx.x * 64;
    float acc = 0.f;
    #pragma unroll 4
    for (int p = base; p < base + 64; p++)
        acc += g_expv[p] * __ldg(mem + p*UNITS + c);
    g_partC[blockIdx.x*256 + c] = acc;
}

// ---------------------------------------------------------------------------
// Transpose memory (4096,256) -> new_mem region of out.
// yoff parameter lets us split into 3 launches (profiler steering: conv1 4th).
// ---------------------------------------------------------------------------
__global__ __launch_bounds__(256) void transpose_kernel(
    const float* __restrict__ mem, float* __restrict__ out, int yoff)
{
    __shared__ float tile[32][33];
    const int p0 = blockIdx.x * 32;
    const int c0 = (blockIdx.y + yoff) * 32;
    const int tx = threadIdx.x, ty = threadIdx.y;
    #pragma unroll
    for (int j = ty; j < 32; j += 8)
        tile[j][tx] = mem[(p0 + j)*UNITS + c0 + tx];
    __syncthreads();
    #pragma unroll
    for (int j = ty; j < 32; j += 8)
        out[512 + (size_t)(c0 + j)*NPIX + p0 + tx] = tile[tx][j];
}

// ---------------------------------------------------------------------------
// Final: reduce c_t, importances, mem update at (x,y); write c_t, r_t
// ---------------------------------------------------------------------------
__global__ __launch_bounds__(256) void final_kernel(
    const float* __restrict__ mem, const float* __restrict__ rec,
    const int* __restrict__ px, const int* __restrict__ py,
    float* __restrict__ out)
{
    __shared__ float s_st[256], s_mold[256];
    __shared__ float red[16];
    __shared__ float s_frac;
    const int c = threadIdx.x;
    const int pos = px[0]*W + py[0];

    float ct = 0.f;
    #pragma unroll 8
    for (int b = 0; b < CTBLK; b++) ct += g_partC[b*256 + c];
    ct *= g_invsum;
    float rt = g_rt[c];
    float st = g_st[c];
    s_st[c] = st;
    s_mold[c] = mem[pos*UNITS + c];
    out[c] = ct;
    out[256 + c] = rt;

    float li = st * ct;
    float gi = st * rt;
    #pragma unroll
    for (int o = 16; o > 0; o >>= 1) {
        li += __shfl_xor_sync(0xffffffffu, li, o);
        gi += __shfl_xor_sync(0xffffffffu, gi, o);
    }
    if ((c & 31) == 0) {
        red[c >> 5] = li;
        red[8 + (c >> 5)] = gi;
    }
    __syncthreads();
    if (c == 0) {
        float L = 0.f, G = 0.f;
        for (int i = 0; i < 8; i++) { L += red[i]; G += red[8 + i]; }
        s_frac = L / (L + G);
    }
    __syncthreads();

    const float frac = s_frac;
    float d = 0.f;
    #pragma unroll 8
    for (int k = 0; k < 256; k++)
        d += (s_mold[k] - s_st[k]) * __ldg(rec + (128 + k)*256 + c);
    out[512 + (size_t)c*NPIX + pos] = s_mold[c] + frac * d;
}

// ---------------------------------------------------------------------------
extern "C" void kernel_launch(void* const* d_in, const int* in_sizes, int n_in,
                              void* d_out, int out_size)
{
    const float* inputs = (const float*)d_in[0];
    const float* mem    = (const float*)d_in[1];
    const float* ck1    = (const float*)d_in[2];
    const float* ck2    = (const float*)d_in[3];
    const float* cd1    = (const float*)d_in[4];
    const float* cd2    = (const float*)d_in[5];
    const float* ctx    = (const float*)d_in[6];
    const float* rec    = (const float*)d_in[7];
    const int*   px     = (const int*)d_in[8];
    const int*   py     = (const int*)d_in[9];
    float* out = (float*)d_out;

    // Launches 1-3: transpose (independent of everything; split so conv1 is 4th)
    transpose_kernel<<<dim3(NPIX / 32, 3), dim3(32, 8)>>>(mem, out, 0);
    transpose_kernel<<<dim3(NPIX / 32, 3), dim3(32, 8)>>>(mem, out, 3);
    transpose_kernel<<<dim3(NPIX / 32, 2), dim3(32, 8)>>>(mem, out, 6);
    // Launch 4: conv1 (ncu captures the 4th launch)
    conv1_kernel<<<dim3(16, 16), 256>>>(mem, ck1);
    conv2_kernel<<<dim3(8, 16), 256>>>(ck2);
    pool_kernel<<<(FLAT + 255) / 256, 256>>>();
    dense1_kernel<<<D1BLK, 256>>>(cd1);
    fuse1_kernel<<<1, 256>>>(inputs, cd2, ctx, rec);
    scores_kernel<<<NPIX / 8, 256>>>(mem);
    softmax_kernel<<<1, 1024>>>();
    ctpart_kernel<<<CTBLK, 256>>>(mem);
    final_kernel<<<1, 256>>>(mem, rec, px, py, out);
}

// round 5
// speedup vs baseline: 1.5897x; 1.0518x over previous
#include <cuda_runtime.h>
#include <cuda_bf16.h>

// ---------------------------------------------------------------------------
// NeuralMapCell pipeline, fp32. Round-4 (289us) config + conv1 rewrite:
// thread = (pixel, 4 oc), ic-split over blockIdx.z, 76% FFMA density.
// Launch order keeps conv1 4th (ncu captures the 4th launch).
// Output: concat( c_t[256], r_t[256], new_mem[256*4096] )
// ---------------------------------------------------------------------------

#define H 64
#define W 64
#define UNITS 256
#define C1OC 32
#define C2OC 64
#define H2 62            // conv2 VALID output
#define HP 61            // pool output
#define FLAT (64*61*61)  // 238144
#define NPIX 4096
#define D1BLK 296
#define D1ROWS 805       // ceil(FLAT / D1BLK)
#define CTBLK 64
#define C1PAD 132        // 128 ic + 4 pad floats (bank-conflict-free LDS.128)
#define C1HALF (NPIX*C1OC)   // 131072 floats per ic-half

// Scratch (device globals; no allocation allowed)
__device__ float g_c1p[2*C1HALF];       // conv1 partials, [z][pixel][oc]
__device__ float g_c2[C2OC*H2*H2];      // [oc][h2][w2]
__device__ float g_flat[FLAT];          // [oc][h][w] of pool
__device__ float g_part1[D1BLK*128];
__device__ float g_rt[256];
__device__ float g_qt[256];
__device__ float g_st[256];
__device__ float g_scores[NPIX];
__device__ float g_expv[NPIX];
__device__ float g_invsum;
__device__ float g_partC[CTBLK*256];

// ---------------------------------------------------------------------------
// conv1: SAME 3x3, 256 -> 32 ch. Tile = 4 rows x 8 cols; grid (8,16,2);
// blockIdx.z = ic half (0:ic<128, 1:ic>=128). 256 threads:
//   o4 = t&7 (oc quad), px = t>>3 (pixel: row = px>>3, col = px&7).
// Per ic-quad: 1 LDS.128 act (4 distinct addrs/warp, padded stride -> no
// conflicts) + 4 LDG.128 weights (one 128B line/warp) + 16 FFMA.
// ---------------------------------------------------------------------------
__global__ __launch_bounds__(256) void conv1_kernel(
    const float* __restrict__ mem, const float* __restrict__ w1)
{
    __shared__ float sa[60*C1PAD];       // 6x10 px halo x 128 ic, ~31.7 KB
    const int bw = blockIdx.x * 8;
    const int bh = blockIdx.y * 4;
    const int zic = blockIdx.z;          // ic half
    const int t = threadIdx.x;

    // Load halo: 60 px x 128 ch as float4 (32 f4 per pixel)
    for (int idx = t; idx < 60*32; idx += 256) {
        int p = idx >> 5;                // pixel 0..59
        int q = idx & 31;                // f4 index in 128 ch
        int r = p / 10, c = p % 10;
        int h = bh + r - 1, w = bw + c - 1;
        float4 v = make_float4(0.f,0.f,0.f,0.f);
        if (h >= 0 && h < H && w >= 0 && w < W)
            v = reinterpret_cast<const float4*>(mem + (h*W + w)*UNITS + zic*128)[q];
        reinterpret_cast<float4*>(sa + p*C1PAD)[q] = v;
    }
    __syncthreads();

    const int o4  = t & 7;
    const int px  = t >> 3;              // 0..31
    const int row = px >> 3;             // 0..3
    const int col = px & 7;              // 0..7

    float4 acc = make_float4(0.f,0.f,0.f,0.f);

    #pragma unroll
    for (int kh = 0; kh < 3; kh++) {
        #pragma unroll
        for (int kw = 0; kw < 3; kw++) {
            const float* __restrict__ wp =
                w1 + ((size_t)((kh*3 + kw)*256 + zic*128))*32 + o4*4;
            const float* __restrict__ ap =
                sa + ((row+kh)*10 + (col+kw))*C1PAD;
            #pragma unroll 4
            for (int ic4 = 0; ic4 < 32; ic4++) {
                float4 a  = *reinterpret_cast<const float4*>(ap + ic4*4);
                float4 w0 = __ldg(reinterpret_cast<const float4*>(wp + (4*ic4+0)*32));
                float4 wa = __ldg(reinterpret_cast<const float4*>(wp + (4*ic4+1)*32));
                float4 wb = __ldg(reinterpret_cast<const float4*>(wp + (4*ic4+2)*32));
                float4 wc = __ldg(reinterpret_cast<const float4*>(wp + (4*ic4+3)*32));
                acc.x += a.x*w0.x + a.y*wa.x + a.z*wb.x + a.w*wc.x;
                acc.y += a.x*w0.y + a.y*wa.y + a.z*wb.y + a.w*wc.y;
                acc.z += a.x*w0.z + a.y*wa.z + a.z*wb.z + a.w*wc.z;
                acc.w += a.x*w0.w + a.y*wa.w + a.z*wb.w + a.w*wc.w;
            }
        }
    }
    const int pix = (bh + row)*W + (bw + col);
    reinterpret_cast<float4*>(g_c1p + zic*C1HALF + pix*C1OC)[o4] = acc;
}

// ---------------------------------------------------------------------------
// conv2: VALID 3x3, 32 -> 64 channels, output 62x62. (round-1 version,
// loader sums the two conv1 ic-half partials)
// ---------------------------------------------------------------------------
__global__ __launch_bounds__(256) void conv2_kernel(
    const float* __restrict__ w2)
{
    __shared__ float s2[60*32];     // 6x10 pixel halo
    const int bw = blockIdx.x * 8;
    const int bh = blockIdx.y * 4;
    const int t = threadIdx.x;

    for (int idx = t; idx < 60*8; idx += 256) {
        int p = idx >> 3;
        int q = idx & 7;
        int ph = p / 10, pw = p % 10;
        int h = bh + ph, w = bw + pw;
        float4 v = make_float4(0.f,0.f,0.f,0.f);
        if (h < H && w < W) {
            int base = (h*W + w)*C1OC;
            float4 v0 = reinterpret_cast<const float4*>(g_c1p + base)[q];
            float4 v1 = reinterpret_cast<const float4*>(g_c1p + C1HALF + base)[q];
            v = make_float4(v0.x+v1.x, v0.y+v1.y, v0.z+v1.z, v0.w+v1.w);
        }
        reinterpret_cast<float4*>(s2 + p*32)[q] = v;
    }
    __syncthreads();

    const int oc = t & 63;
    const int pg = t >> 6;
    float acc[8];
    #pragma unroll
    for (int i = 0; i < 8; i++) acc[i] = 0.f;

    #pragma unroll
    for (int kh = 0; kh < 3; kh++) {
        #pragma unroll
        for (int kw = 0; kw < 3; kw++) {
            const float* __restrict__ wp = w2 + ((kh*3 + kw)*32)*64 + oc;
            const float* __restrict__ sp = s2 + ((pg+kh)*10 + kw)*32;
            #pragma unroll 4
            for (int ic = 0; ic < 32; ic++) {
                float wv = __ldg(wp + ic*64);
                #pragma unroll
                for (int pw = 0; pw < 8; pw++)
                    acc[pw] += wv * sp[pw*32 + ic];
            }
        }
    }
    const int h2 = bh + pg;
    if (h2 < H2) {
        #pragma unroll
        for (int pw = 0; pw < 8; pw++) {
            int w2i = bw + pw;
            if (w2i < H2)
                g_c2[oc*(H2*H2) + h2*H2 + w2i] = acc[pw];
        }
    }
}

// ---------------------------------------------------------------------------
// 2x2 sum pool (stride 1) * 0.25 -> flat
// ---------------------------------------------------------------------------
__global__ __launch_bounds__(256) void pool_kernel()
{
    int idx = blockIdx.x * 256 + threadIdx.x;
    if (idx >= FLAT) return;
    int oc = idx / (HP*HP);
    int r = idx - oc*(HP*HP);
    int h = r / HP;
    int w = r - h*HP;
    const float* base = g_c2 + oc*(H2*H2) + h*H2 + w;
    g_flat[idx] = 0.25f * (base[0] + base[1] + base[H2] + base[H2+1]);
}

// ---------------------------------------------------------------------------
// dense1: flat(1x238144) @ W1(238144x128). Per-lane float4 loads, 4-row unroll.
// ---------------------------------------------------------------------------
__global__ __launch_bounds__(256) void dense1_kernel(const float* __restrict__ W1)
{
    const int t = threadIdx.x;
    const int lane = t & 31;
    const int wid  = t >> 5;
    const int row0 = blockIdx.x * D1ROWS;
    int lim = row0 + D1ROWS;
    if (lim > FLAT) lim = FLAT;

    float4 acc = make_float4(0.f,0.f,0.f,0.f);
    for (int k = 0; k < 104; k += 4) {          // 104*8 = 832 >= 805 rows
        #pragma unroll
        for (int u = 0; u < 4; u++) {
            int i = row0 + wid + 8*(k + u);
            if (i < lim) {
                float f = __ldg(g_flat + i);
                float4 wv = __ldg(reinterpret_cast<const float4*>(W1 + (size_t)i*128) + lane);
                acc.x += f*wv.x; acc.y += f*wv.y; acc.z += f*wv.z; acc.w += f*wv.w;
            }
        }
    }
    __shared__ float4 sred[256];
    sred[wid*32 + lane] = acc;
    __syncthreads();
    if (t < 32) {
        float4 s = sred[t];
        #pragma unroll
        for (int w = 1; w < 8; w++) {
            float4 v = sred[w*32 + t];
            s.x += v.x; s.y += v.y; s.z += v.z; s.w += v.w;
        }
        reinterpret_cast<float4*>(g_part1 + blockIdx.x*128)[t] = s;
    }
}

// ---------------------------------------------------------------------------
// fuse1: reduce r128; r_t = r128@W2; q_t = [in,r_t]@ctx; s_t = in@rec[:128]
// ---------------------------------------------------------------------------
__global__ __launch_bounds__(256) void fuse1_kernel(
    const float* __restrict__ inputs, const float* __restrict__ W2,
    const float* __restrict__ ctx, const float* __restrict__ rec)
{
    __shared__ float s_r128[128];
    __shared__ float s_rt[256];
    __shared__ float s_in[128];
    const int t = threadIdx.x;

    if (t < 128) {
        float a = 0.f;
        #pragma unroll 8
        for (int b = 0; b < D1BLK; b++) a += g_part1[b*128 + t];
        s_r128[t] = a;
        s_in[t] = inputs[t];
    }
    __syncthreads();

    float rt = 0.f;
    #pragma unroll 8
    for (int k = 0; k < 128; k++) rt += s_r128[k] * W2[k*256 + t];
    s_rt[t] = rt;
    g_rt[t] = rt;
    __syncthreads();

    float q = 0.f, sv = 0.f;
    #pragma unroll 8
    for (int k = 0; k < 128; k++) {
        float iv = s_in[k];
        q  += iv * ctx[k*256 + t];
        sv += iv * rec[k*256 + t];
    }
    #pragma unroll 8
    for (int k = 0; k < 256; k++)
        q += s_rt[k] * ctx[(128 + k)*256 + t];
    g_qt[t] = q;
    g_st[t] = sv;
}

// ---------------------------------------------------------------------------
// scores[p] = dot(q_t, memory[p,:])  — warp per row
// ---------------------------------------------------------------------------
__global__ __launch_bounds__(256) void scores_kernel(const float* __restrict__ mem)
{
    __shared__ float4 sq[64];
    const int t = threadIdx.x;
    if (t < 64) sq[t] = reinterpret_cast<const float4*>(g_qt)[t];
    __syncthreads();

    const int lane = t & 31;
    const int p = blockIdx.x * 8 + (t >> 5);
    const float4* mp = reinterpret_cast<const float4*>(mem + p*UNITS);
    float4 m0 = mp[lane];
    float4 m1 = mp[lane + 32];
    float4 q0 = sq[lane];
    float4 q1 = sq[lane + 32];
    float acc = m0.x*q0.x + m0.y*q0.y + m0.z*q0.z + m0.w*q0.w
              + m1.x*q1.x + m1.y*q1.y + m1.z*q1.z + m1.w*q1.w;
    #pragma unroll
    for (int o = 16; o > 0; o >>= 1)
        acc += __shfl_down_sync(0xffffffffu, acc, o);
    if (lane == 0) g_scores[p] = acc;
}

// ---------------------------------------------------------------------------
// softmax over 4096 scores (single block)
// ---------------------------------------------------------------------------
__global__ __launch_bounds__(1024) void softmax_kernel()
{
    __shared__ float red[32];
    const int t = threadIdx.x;
    float4 v = reinterpret_cast<const float4*>(g_scores)[t];
    float m = fmaxf(fmaxf(v.x, v.y), fmaxf(v.z, v.w));
    #pragma unroll
    for (int o = 16; o > 0; o >>= 1)
        m = fmaxf(m, __shfl_xor_sync(0xffffffffu, m, o));
    if ((t & 31) == 0) red[t >> 5] = m;
    __syncthreads();
    if (t < 32) {
        float mm = red[t];
        #pragma unroll
        for (int o = 16; o > 0; o >>= 1)
            mm = fmaxf(mm, __shfl_xor_sync(0xffffffffu, mm, o));
        red[t] = mm;
    }
    __syncthreads();
    const float gmax = red[0];
    __syncthreads();

    float4 e;
    e.x = expf(v.x - gmax); e.y = expf(v.y - gmax);
    e.z = expf(v.z - gmax); e.w = expf(v.w - gmax);
    reinterpret_cast<float4*>(g_expv)[t] = e;
    float s = e.x + e.y + e.z + e.w;
    #pragma unroll
    for (int o = 16; o > 0; o >>= 1)
        s += __shfl_xor_sync(0xffffffffu, s, o);
    if ((t & 31) == 0) red[t >> 5] = s;
    __syncthreads();
    if (t == 0) {
        float ss = 0.f;
        for (int i = 0; i < 32; i++) ss += red[i];
        g_invsum = 1.f / ss;
    }
}

// ---------------------------------------------------------------------------
// c_t partials: sum_p expv[p] * memory[p,:], 64 blocks of 64 rows
// ---------------------------------------------------------------------------
__global__ __launch_bounds__(256) void ctpart_kernel(const float* __restrict__ mem)
{
    const int c = threadIdx.x;
    const int base = blockIdx.x * 64;
    float acc = 0.f;
    #pragma unroll 4
    for (int p = base; p < base + 64; p++)
        acc += g_expv[p] * __ldg(mem + p*UNITS + c);
    g_partC[blockIdx.x*256 + c] = acc;
}

// ---------------------------------------------------------------------------
// Transpose memory (4096,256) -> new_mem region of out (split into 3 launches)
// ---------------------------------------------------------------------------
__global__ __launch_bounds__(256) void transpose_kernel(
    const float* __restrict__ mem, float* __restrict__ out, int yoff)
{
    __shared__ float tile[32][33];
    const int p0 = blockIdx.x * 32;
    const int c0 = (blockIdx.y + yoff) * 32;
    const int tx = threadIdx.x, ty = threadIdx.y;
    #pragma unroll
    for (int j = ty; j < 32; j += 8)
        tile[j][tx] = mem[(p0 + j)*UNITS + c0 + tx];
    __syncthreads();
    #pragma unroll
    for (int j = ty; j < 32; j += 8)
        out[512 + (size_t)(c0 + j)*NPIX + p0 + tx] = tile[tx][j];
}

// ---------------------------------------------------------------------------
// Final: reduce c_t, importances, mem update at (x,y); write c_t, r_t
// ---------------------------------------------------------------------------
__global__ __launch_bounds__(256) void final_kernel(
    const float* __restrict__ mem, const float* __restrict__ rec,
    const int* __restrict__ px, const int* __restrict__ py,
    float* __restrict__ out)
{
    __shared__ float s_st[256], s_mold[256];
    __shared__ float red[16];
    __shared__ float s_frac;
    const int c = threadIdx.x;
    const int pos = px[0]*W + py[0];

    float ct = 0.f;
    #pragma unroll 8
    for (int b = 0; b < CTBLK; b++) ct += g_partC[b*256 + c];
    ct *= g_invsum;
    float rt = g_rt[c];
    float st = g_st[c];
    s_st[c] = st;
    s_mold[c] = mem[pos*UNITS + c];
    out[c] = ct;
    out[256 + c] = rt;

    float li = st * ct;
    float gi = st * rt;
    #pragma unroll
    for (int o = 16; o > 0; o >>= 1) {
        li += __shfl_xor_sync(0xffffffffu, li, o);
        gi += __shfl_xor_sync(0xffffffffu, gi, o);
    }
    if ((c & 31) == 0) {
        red[c >> 5] = li;
        red[8 + (c >> 5)] = gi;
    }
    __syncthreads();
    if (c == 0) {
        float L = 0.f, G = 0.f;
        for (int i = 0; i < 8; i++) { L += red[i]; G += red[8 + i]; }
        s_frac = L / (L + G);
    }
    __syncthreads();

    const float frac = s_frac;
    float d = 0.f;
    #pragma unroll 8
    for (int k = 0; k < 256; k++)
        d += (s_mold[k] - s_st[k]) * __ldg(rec + (128 + k)*256 + c);
    out[512 + (size_t)c*NPIX + pos] = s_mold[c] + frac * d;
}

// ---------------------------------------------------------------------------
extern "C" void kernel_launch(void* const* d_in, const int* in_sizes, int n_in,
                              void* d_out, int out_size)
{
    const float* inputs = (const float*)d_in[0];
    const float* mem    = (const float*)d_in[1];
    const float* ck1    = (const float*)d_in[2];
    const float* ck2    = (const float*)d_in[3];
    const float* cd1    = (const float*)d_in[4];
    const float* cd2    = (const float*)d_in[5];
    const float* ctx    = (const float*)d_in[6];
    const float* rec    = (const float*)d_in[7];
    const int*   px     = (const int*)d_in[8];
    const int*   py     = (const int*)d_in[9];
    float* out = (float*)d_out;

    // Launches 1-3: transpose (independent; split so conv1 is 4th for ncu)
    transpose_kernel<<<dim3(NPIX / 32, 3), dim3(32, 8)>>>(mem, out, 0);
    transpose_kernel<<<dim3(NPIX / 32, 3), dim3(32, 8)>>>(mem, out, 3);
    transpose_kernel<<<dim3(NPIX / 32, 2), dim3(32, 8)>>>(mem, out, 6);
    // Launch 4: conv1 (profiled)
    conv1_kernel<<<dim3(8, 16, 2), 256>>>(mem, ck1);
    conv2_kernel<<<dim3(8, 16), 256>>>(ck2);
    pool_kernel<<<(FLAT + 255) / 256, 256>>>();
    dense1_kernel<<<D1BLK, 256>>>(cd1);
    fuse1_kernel<<<1, 256>>>(inputs, cd2, ctx, rec);
    scores_kernel<<<NPIX / 8, 256>>>(mem);
    softmax_kernel<<<1, 1024>>>();
    ctpart_kernel<<<CTBLK, 256>>>(mem);
    final_kernel<<<1, 256>>>(mem, rec, px, py, out);
}

// round 6
// speedup vs baseline: 1.9333x; 1.2162x over previous
#include <cuda_runtime.h>
#include <cuda_bf16.h>

// ---------------------------------------------------------------------------
// NeuralMapCell pipeline, fp32. Round-5 config + conv1 v3:
// 2 px/thread, ic-quartered (grid 512), 84% FFMA density, 128 threads.
// Launch order keeps conv1 4th (ncu captures the 4th launch).
// Output: concat( c_t[256], r_t[256], new_mem[256*4096] )
// ---------------------------------------------------------------------------

#define H 64
#define W 64
#define UNITS 256
#define C1OC 32
#define C2OC 64
#define H2 62            // conv2 VALID output
#define HP 61            // pool output
#define FLAT (64*61*61)  // 238144
#define NPIX 4096
#define D1BLK 296
#define D1ROWS 805       // ceil(FLAT / D1BLK)
#define CTBLK 64
#define C1PITCH 68       // 64 ic + 4 pad floats per pixel (bank-spread LDS.128)
#define C1Q (NPIX*C1OC)  // 131072 floats per ic-quarter

// Scratch (device globals; no allocation allowed)
__device__ float g_c1p[4*C1Q];          // conv1 partials, [z][pixel][oc]
__device__ float g_c2[C2OC*H2*H2];      // [oc][h2][w2]
__device__ float g_flat[FLAT];          // [oc][h][w] of pool
__device__ float g_part1[D1BLK*128];
__device__ float g_rt[256];
__device__ float g_qt[256];
__device__ float g_st[256];
__device__ float g_scores[NPIX];
__device__ float g_expv[NPIX];
__device__ float g_invsum;
__device__ float g_partC[CTBLK*256];

// ---------------------------------------------------------------------------
// conv1: SAME 3x3, 256 -> 32 ch. Tile 4x8 px; grid (8,16,4); z = ic quarter.
// 128 threads: o4 = t&7 (oc quad), pp = t>>3 -> row = pp>>2, colpair = pp&3.
// Each thread: 2 adjacent pixels, float4 acc each.
// Per ic4: 2 LDS.128 (4 distinct addrs/warp, pitch-68 -> conflict-free)
//        + 4 LDG.128 weights (one 128B line/warp) + 32 FFMA.
// ---------------------------------------------------------------------------
__global__ __launch_bounds__(128) void conv1_kernel(
    const float* __restrict__ mem, const float* __restrict__ w1)
{
    __shared__ float sa[60*C1PITCH];     // 6x10 px halo x 64 ic, ~16.3 KB
    const int bw = blockIdx.x * 8;
    const int bh = blockIdx.y * 4;
    const int zic = blockIdx.z;          // ic quarter (64 ch)
    const int t = threadIdx.x;

    // Load halo: 60 px x 64 ch as float4 (16 f4 per pixel)
    for (int idx = t; idx < 60*16; idx += 128) {
        int p = idx >> 4;                // pixel 0..59
        int q = idx & 15;                // f4 index within 64 ch
        int r = p / 10, c = p % 10;
        int h = bh + r - 1, w = bw + c - 1;
        float4 v = make_float4(0.f,0.f,0.f,0.f);
        if (h >= 0 && h < H && w >= 0 && w < W)
            v = reinterpret_cast<const float4*>(mem + (h*W + w)*UNITS + zic*64)[q];
        reinterpret_cast<float4*>(sa + p*C1PITCH)[q] = v;
    }
    __syncthreads();

    const int o4   = t & 7;
    const int pp   = t >> 3;             // 0..15
    const int row  = pp >> 2;            // 0..3
    const int col0 = (pp & 3) * 2;       // 0,2,4,6
    float4 acc0 = make_float4(0.f,0.f,0.f,0.f);
    float4 acc1 = make_float4(0.f,0.f,0.f,0.f);

    #pragma unroll
    for (int kh = 0; kh < 3; kh++) {
        #pragma unroll
        for (int kw = 0; kw < 3; kw++) {
            const float* __restrict__ wp =
                w1 + ((size_t)((kh*3 + kw)*256 + zic*64))*32 + o4*4;
            const float* __restrict__ ap0 =
                sa + ((row+kh)*10 + (col0+kw))*C1PITCH;
            const float* __restrict__ ap1 = ap0 + C1PITCH;
            #pragma unroll 4
            for (int ic4 = 0; ic4 < 16; ic4++) {
                float4 a0 = *reinterpret_cast<const float4*>(ap0 + ic4*4);
                float4 a1 = *reinterpret_cast<const float4*>(ap1 + ic4*4);
                float4 w0 = __ldg(reinterpret_cast<const float4*>(wp + (4*ic4+0)*32));
                float4 wa = __ldg(reinterpret_cast<const float4*>(wp + (4*ic4+1)*32));
                float4 wb = __ldg(reinterpret_cast<const float4*>(wp + (4*ic4+2)*32));
                float4 wc = __ldg(reinterpret_cast<const float4*>(wp + (4*ic4+3)*32));
                acc0.x += a0.x*w0.x + a0.y*wa.x + a0.z*wb.x + a0.w*wc.x;
                acc0.y += a0.x*w0.y + a0.y*wa.y + a0.z*wb.y + a0.w*wc.y;
                acc0.z += a0.x*w0.z + a0.y*wa.z + a0.z*wb.z + a0.w*wc.z;
                acc0.w += a0.x*w0.w + a0.y*wa.w + a0.z*wb.w + a0.w*wc.w;
                acc1.x += a1.x*w0.x + a1.y*wa.x + a1.z*wb.x + a1.w*wc.x;
                acc1.y += a1.x*w0.y + a1.y*wa.y + a1.z*wb.y + a1.w*wc.y;
                acc1.z += a1.x*w0.z + a1.y*wa.z + a1.z*wb.z + a1.w*wc.z;
                acc1.w += a1.x*w0.w + a1.y*wa.w + a1.z*wb.w + a1.w*wc.w;
            }
        }
    }
    const int pix0 = (bh + row)*W + (bw + col0);
    reinterpret_cast<float4*>(g_c1p + zic*C1Q + (size_t)pix0*C1OC)[o4] = acc0;
    reinterpret_cast<float4*>(g_c1p + zic*C1Q + (size_t)(pix0+1)*C1OC)[o4] = acc1;
}

// ---------------------------------------------------------------------------
// conv2: VALID 3x3, 32 -> 64 channels, output 62x62.
// Loader sums the 4 conv1 ic-quarter partials.
// ---------------------------------------------------------------------------
__global__ __launch_bounds__(256) void conv2_kernel(
    const float* __restrict__ w2)
{
    __shared__ float s2[60*32];     // 6x10 pixel halo
    const int bw = blockIdx.x * 8;
    const int bh = blockIdx.y * 4;
    const int t = threadIdx.x;

    for (int idx = t; idx < 60*8; idx += 256) {
        int p = idx >> 3;
        int q = idx & 7;
        int ph = p / 10, pw = p % 10;
        int h = bh + ph, w = bw + pw;
        float4 v = make_float4(0.f,0.f,0.f,0.f);
        if (h < H && w < W) {
            int base = (h*W + w)*C1OC;
            float4 v0 = reinterpret_cast<const float4*>(g_c1p + base)[q];
            float4 v1 = reinterpret_cast<const float4*>(g_c1p + C1Q + base)[q];
            float4 v2 = reinterpret_cast<const float4*>(g_c1p + 2*C1Q + base)[q];
            float4 v3 = reinterpret_cast<const float4*>(g_c1p + 3*C1Q + base)[q];
            v = make_float4(v0.x+v1.x+v2.x+v3.x, v0.y+v1.y+v2.y+v3.y,
                            v0.z+v1.z+v2.z+v3.z, v0.w+v1.w+v2.w+v3.w);
        }
        reinterpret_cast<float4*>(s2 + p*32)[q] = v;
    }
    __syncthreads();

    const int oc = t & 63;
    const int pg = t >> 6;
    float acc[8];
    #pragma unroll
    for (int i = 0; i < 8; i++) acc[i] = 0.f;

    #pragma unroll
    for (int kh = 0; kh < 3; kh++) {
        #pragma unroll
        for (int kw = 0; kw < 3; kw++) {
            const float* __restrict__ wp = w2 + ((kh*3 + kw)*32)*64 + oc;
            const float* __restrict__ sp = s2 + ((pg+kh)*10 + kw)*32;
            #pragma unroll 4
            for (int ic = 0; ic < 32; ic++) {
                float wv = __ldg(wp + ic*64);
                #pragma unroll
                for (int pw = 0; pw < 8; pw++)
                    acc[pw] += wv * sp[pw*32 + ic];
            }
        }
    }
    const int h2 = bh + pg;
    if (h2 < H2) {
        #pragma unroll
        for (int pw = 0; pw < 8; pw++) {
            int w2i = bw + pw;
            if (w2i < H2)
                g_c2[oc*(H2*H2) + h2*H2 + w2i] = acc[pw];
        }
    }
}

// ---------------------------------------------------------------------------
// 2x2 sum pool (stride 1) * 0.25 -> flat
// ---------------------------------------------------------------------------
__global__ __launch_bounds__(256) void pool_kernel()
{
    int idx = blockIdx.x * 256 + threadIdx.x;
    if (idx >= FLAT) return;
    int oc = idx / (HP*HP);
    int r = idx - oc*(HP*HP);
    int h = r / HP;
    int w = r - h*HP;
    const float* base = g_c2 + oc*(H2*H2) + h*H2 + w;
    g_flat[idx] = 0.25f * (base[0] + base[1] + base[H2] + base[H2+1]);
}

// ---------------------------------------------------------------------------
// dense1: flat(1x238144) @ W1(238144x128). Per-lane float4 loads, 4-row unroll.
// ---------------------------------------------------------------------------
__global__ __launch_bounds__(256) void dense1_kernel(const float* __restrict__ W1)
{
    const int t = threadIdx.x;
    const int lane = t & 31;
    const int wid  = t >> 5;
    const int row0 = blockIdx.x * D1ROWS;
    int lim = row0 + D1ROWS;
    if (lim > FLAT) lim = FLAT;

    float4 acc = make_float4(0.f,0.f,0.f,0.f);
    for (int k = 0; k < 104; k += 4) {          // 104*8 = 832 >= 805 rows
        #pragma unroll
        for (int u = 0; u < 4; u++) {
            int i = row0 + wid + 8*(k + u);
            if (i < lim) {
                float f = __ldg(g_flat + i);
                float4 wv = __ldg(reinterpret_cast<const float4*>(W1 + (size_t)i*128) + lane);
                acc.x += f*wv.x; acc.y += f*wv.y; acc.z += f*wv.z; acc.w += f*wv.w;
            }
        }
    }
    __shared__ float4 sred[256];
    sred[wid*32 + lane] = acc;
    __syncthreads();
    if (t < 32) {
        float4 s = sred[t];
        #pragma unroll
        for (int w = 1; w < 8; w++) {
            float4 v = sred[w*32 + t];
            s.x += v.x; s.y += v.y; s.z += v.z; s.w += v.w;
        }
        reinterpret_cast<float4*>(g_part1 + blockIdx.x*128)[t] = s;
    }
}

// ---------------------------------------------------------------------------
// fuse1: reduce r128; r_t = r128@W2; q_t = [in,r_t]@ctx; s_t = in@rec[:128]
// ---------------------------------------------------------------------------
__global__ __launch_bounds__(256) void fuse1_kernel(
    const float* __restrict__ inputs, const float* __restrict__ W2,
    const float* __restrict__ ctx, const float* __restrict__ rec)
{
    __shared__ float s_r128[128];
    __shared__ float s_rt[256];
    __shared__ float s_in[128];
    const int t = threadIdx.x;

    if (t < 128) {
        float a = 0.f;
        #pragma unroll 8
        for (int b = 0; b < D1BLK; b++) a += g_part1[b*128 + t];
        s_r128[t] = a;
        s_in[t] = inputs[t];
    }
    __syncthreads();

    float rt = 0.f;
    #pragma unroll 8
    for (int k = 0; k < 128; k++) rt += s_r128[k] * W2[k*256 + t];
    s_rt[t] = rt;
    g_rt[t] = rt;
    __syncthreads();

    float q = 0.f, sv = 0.f;
    #pragma unroll 8
    for (int k = 0; k < 128; k++) {
        float iv = s_in[k];
        q  += iv * ctx[k*256 + t];
        sv += iv * rec[k*256 + t];
    }
    #pragma unroll 8
    for (int k = 0; k < 256; k++)
        q += s_rt[k] * ctx[(128 + k)*256 + t];
    g_qt[t] = q;
    g_st[t] = sv;
}

// ---------------------------------------------------------------------------
// scores[p] = dot(q_t, memory[p,:])  — warp per row
// ---------------------------------------------------------------------------
__global__ __launch_bounds__(256) void scores_kernel(const float* __restrict__ mem)
{
    __shared__ float4 sq[64];
    const int t = threadIdx.x;
    if (t < 64) sq[t] = reinterpret_cast<const float4*>(g_qt)[t];
    __syncthreads();

    const int lane = t & 31;
    const int p = blockIdx.x * 8 + (t >> 5);
    const float4* mp = reinterpret_cast<const float4*>(mem + p*UNITS);
    float4 m0 = mp[lane];
    float4 m1 = mp[lane + 32];
    float4 q0 = sq[lane];
    float4 q1 = sq[lane + 32];
    float acc = m0.x*q0.x + m0.y*q0.y + m0.z*q0.z + m0.w*q0.w
              + m1.x*q1.x + m1.y*q1.y + m1.z*q1.z + m1.w*q1.w;
    #pragma unroll
    for (int o = 16; o > 0; o >>= 1)
        acc += __shfl_down_sync(0xffffffffu, acc, o);
    if (lane == 0) g_scores[p] = acc;
}

// ---------------------------------------------------------------------------
// softmax over 4096 scores (single block)
// ---------------------------------------------------------------------------
__global__ __launch_bounds__(1024) void softmax_kernel()
{
    __shared__ float red[32];
    const int t = threadIdx.x;
    float4 v = reinterpret_cast<const float4*>(g_scores)[t];
    float m = fmaxf(fmaxf(v.x, v.y), fmaxf(v.z, v.w));
    #pragma unroll
    for (int o = 16; o > 0; o >>= 1)
        m = fmaxf(m, __shfl_xor_sync(0xffffffffu, m, o));
    if ((t & 31) == 0) red[t >> 5] = m;
    __syncthreads();
    if (t < 32) {
        float mm = red[t];
        #pragma unroll
        for (int o = 16; o > 0; o >>= 1)
            mm = fmaxf(mm, __shfl_xor_sync(0xffffffffu, mm, o));
        red[t] = mm;
    }
    __syncthreads();
    const float gmax = red[0];
    __syncthreads();

    float4 e;
    e.x = expf(v.x - gmax); e.y = expf(v.y - gmax);
    e.z = expf(v.z - gmax); e.w = expf(v.w - gmax);
    reinterpret_cast<float4*>(g_expv)[t] = e;
    float s = e.x + e.y + e.z + e.w;
    #pragma unroll
    for (int o = 16; o > 0; o >>= 1)
        s += __shfl_xor_sync(0xffffffffu, s, o);
    if ((t & 31) == 0) red[t >> 5] = s;
    __syncthreads();
    if (t == 0) {
        float ss = 0.f;
        for (int i = 0; i < 32; i++) ss += red[i];
        g_invsum = 1.f / ss;
    }
}

// ---------------------------------------------------------------------------
// c_t partials: sum_p expv[p] * memory[p,:], 64 blocks of 64 rows
// ---------------------------------------------------------------------------
__global__ __launch_bounds__(256) void ctpart_kernel(const float* __restrict__ mem)
{
    const int c = threadIdx.x;
    const int base = blockIdx.x * 64;
    float acc = 0.f;
    #pragma unroll 4
    for (int p = base; p < base + 64; p++)
        acc += g_expv[p] * __ldg(mem + p*UNITS + c);
    g_partC[blockIdx.x*256 + c] = acc;
}

// ---------------------------------------------------------------------------
// Transpose memory (4096,256) -> new_mem region of out (split into 3 launches)
// ---------------------------------------------------------------------------
__global__ __launch_bounds__(256) void transpose_kernel(
    const float* __restrict__ mem, float* __restrict__ out, int yoff)
{
    __shared__ float tile[32][33];
    const int p0 = blockIdx.x * 32;
    const int c0 = (blockIdx.y + yoff) * 32;
    const int tx = threadIdx.x, ty = threadIdx.y;
    #pragma unroll
    for (int j = ty; j < 32; j += 8)
        tile[j][tx] = mem[(p0 + j)*UNITS + c0 + tx];
    __syncthreads();
    #pragma unroll
    for (int j = ty; j < 32; j += 8)
        out[512 + (size_t)(c0 + j)*NPIX + p0 + tx] = tile[tx][j];
}

// ---------------------------------------------------------------------------
// Final: reduce c_t, importances, mem update at (x,y); write c_t, r_t
// ---------------------------------------------------------------------------
__global__ __launch_bounds__(256) void final_kernel(
    const float* __restrict__ mem, const float* __restrict__ rec,
    const int* __restrict__ px, const int* __restrict__ py,
    float* __restrict__ out)
{
    __shared__ float s_st[256], s_mold[256];
    __shared__ float red[16];
    __shared__ float s_frac;
    const int c = threadIdx.x;
    const int pos = px[0]*W + py[0];

    float ct = 0.f;
    #pragma unroll 8
    for (int b = 0; b < CTBLK; b++) ct += g_partC[b*256 + c];
    ct *= g_invsum;
    float rt = g_rt[c];
    float st = g_st[c];
    s_st[c] = st;
    s_mold[c] = mem[pos*UNITS + c];
    out[c] = ct;
    out[256 + c] = rt;

    float li = st * ct;
    float gi = st * rt;
    #pragma unroll
    for (int o = 16; o > 0; o >>= 1) {
        li += __shfl_xor_sync(0xffffffffu, li, o);
        gi += __shfl_xor_sync(0xffffffffu, gi, o);
    }
    if ((c & 31) == 0) {
        red[c >> 5] = li;
        red[8 + (c >> 5)] = gi;
    }
    __syncthreads();
    if (c == 0) {
        float L = 0.f, G = 0.f;
        for (int i = 0; i < 8; i++) { L += red[i]; G += red[8 + i]; }
        s_frac = L / (L + G);
    }
    __syncthreads();

    const float frac = s_frac;
    float d = 0.f;
    #pragma unroll 8
    for (int k = 0; k < 256; k++)
        d += (s_mold[k] - s_st[k]) * __ldg(rec + (128 + k)*256 + c);
    out[512 + (size_t)c*NPIX + pos] = s_mold[c] + frac * d;
}

// ---------------------------------------------------------------------------
extern "C" void kernel_launch(void* const* d_in, const int* in_sizes, int n_in,
                              void* d_out, int out_size)
{
    const float* inputs = (const float*)d_in[0];
    const float* mem    = (const float*)d_in[1];
    const float* ck1    = (const float*)d_in[2];
    const float* ck2    = (const float*)d_in[3];
    const float* cd1    = (const float*)d_in[4];
    const float* cd2    = (const float*)d_in[5];
    const float* ctx    = (const float*)d_in[6];
    const float* rec    = (const float*)d_in[7];
    const int*   px     = (const int*)d_in[8];
    const int*   py     = (const int*)d_in[9];
    float* out = (float*)d_out;

    // Launches 1-3: transpose (independent; split so conv1 is 4th for ncu)
    transpose_kernel<<<dim3(NPIX / 32, 3), dim3(32, 8)>>>(mem, out, 0);
    transpose_kernel<<<dim3(NPIX / 32, 3), dim3(32, 8)>>>(mem, out, 3);
    transpose_kernel<<<dim3(NPIX / 32, 2), dim3(32, 8)>>>(mem, out, 6);
    // Launch 4: conv1 (profiled)
    conv1_kernel<<<dim3(8, 16, 4), 128>>>(mem, ck1);
    conv2_kernel<<<dim3(8, 16), 256>>>(ck2);
    pool_kernel<<<(FLAT + 255) / 256, 256>>>();
    dense1_kernel<<<D1BLK, 256>>>(cd1);
    fuse1_kernel<<<1, 256>>>(inputs, cd2, ctx, rec);
    scores_kernel<<<NPIX / 8, 256>>>(mem);
    softmax_kernel<<<1, 1024>>>();
    ctpart_kernel<<<CTBLK, 256>>>(mem);
    final_kernel<<<1, 256>>>(mem, rec, px, py, out);
}

// round 7
// speedup vs baseline: 2.0847x; 1.0783x over previous
#include <cuda_runtime.h>
#include <cuda_bf16.h>

// ---------------------------------------------------------------------------
// NeuralMapCell pipeline, fp32. Round-6 + conv1 ic-split-8 + conv2 retile.
// Launch order: transpose, conv1, c1red, conv2 (4th -> profiled), ...
// Output: concat( c_t[256], r_t[256], new_mem[256*4096] )
// ---------------------------------------------------------------------------

#define H 64
#define W 64
#define UNITS 256
#define C1OC 32
#define C2OC 64
#define H2 62            // conv2 VALID output
#define HP 61            // pool output
#define FLAT (64*61*61)  // 238144
#define NPIX 4096
#define D1BLK 296
#define D1ROWS 805       // ceil(FLAT / D1BLK)
#define CTBLK 64
#define C1PITCH 36       // 32 ic + 4 pad floats per pixel (bank-spread LDS.128)
#define C1Q (NPIX*C1OC)  // 131072 floats per ic-eighth

// Scratch (device globals; no allocation allowed)
__device__ float g_c1p[8*C1Q];          // conv1 partials, [z][pixel][oc]
__device__ float g_c1[NPIX*C1OC];       // reduced conv1 output [pixel][oc]
__device__ float g_c2[C2OC*H2*H2];      // [oc][h2][w2]
__device__ float g_flat[FLAT];          // [oc][h][w] of pool
__device__ float g_part1[D1BLK*128];
__device__ float g_rt[256];
__device__ float g_qt[256];
__device__ float g_st[256];
__device__ float g_scores[NPIX];
__device__ float g_expv[NPIX];
__device__ float g_invsum;
__device__ float g_partC[CTBLK*256];

// ---------------------------------------------------------------------------
// conv1: SAME 3x3, 256 -> 32 ch. Tile 4x8 px; grid (8,16,8); z = ic eighth.
// 128 threads: o4 = t&7 (oc quad), pp = t>>3 -> row = pp>>2, col0 = (pp&3)*2.
// Per ic4: 2 LDS.128 + 4 LDG.128 weights + 32 FFMA.
// ---------------------------------------------------------------------------
__global__ __launch_bounds__(128) void conv1_kernel(
    const float* __restrict__ mem, const float* __restrict__ w1)
{
    __shared__ float sa[60*C1PITCH];     // 6x10 px halo x 32 ic, ~8.6 KB
    const int bw = blockIdx.x * 8;
    const int bh = blockIdx.y * 4;
    const int zic = blockIdx.z;          // ic eighth (32 ch)
    const int t = threadIdx.x;

    // Load halo: 60 px x 32 ch as float4 (8 f4 per pixel)
    for (int idx = t; idx < 60*8; idx += 128) {
        int p = idx >> 3;                // pixel 0..59
        int q = idx & 7;                 // f4 index within 32 ch
        int r = p / 10, c = p % 10;
        int h = bh + r - 1, w = bw + c - 1;
        float4 v = make_float4(0.f,0.f,0.f,0.f);
        if (h >= 0 && h < H && w >= 0 && w < W)
            v = reinterpret_cast<const float4*>(mem + (h*W + w)*UNITS + zic*32)[q];
        reinterpret_cast<float4*>(sa + p*C1PITCH)[q] = v;
    }
    __syncthreads();

    const int o4   = t & 7;
    const int pp   = t >> 3;             // 0..15
    const int row  = pp >> 2;            // 0..3
    const int col0 = (pp & 3) * 2;       // 0,2,4,6
    float4 acc0 = make_float4(0.f,0.f,0.f,0.f);
    float4 acc1 = make_float4(0.f,0.f,0.f,0.f);

    #pragma unroll
    for (int kh = 0; kh < 3; kh++) {
        #pragma unroll
        for (int kw = 0; kw < 3; kw++) {
            const float* __restrict__ wp =
                w1 + ((size_t)((kh*3 + kw)*256 + zic*32))*32 + o4*4;
            const float* __restrict__ ap0 =
                sa + ((row+kh)*10 + (col0+kw))*C1PITCH;
            const float* __restrict__ ap1 = ap0 + C1PITCH;
            #pragma unroll
            for (int ic4 = 0; ic4 < 8; ic4++) {
                float4 a0 = *reinterpret_cast<const float4*>(ap0 + ic4*4);
                float4 a1 = *reinterpret_cast<const float4*>(ap1 + ic4*4);
                float4 w0 = __ldg(reinterpret_cast<const float4*>(wp + (4*ic4+0)*32));
                float4 wa = __ldg(reinterpret_cast<const float4*>(wp + (4*ic4+1)*32));
                float4 wb = __ldg(reinterpret_cast<const float4*>(wp + (4*ic4+2)*32));
                float4 wc = __ldg(reinterpret_cast<const float4*>(wp + (4*ic4+3)*32));
                acc0.x += a0.x*w0.x + a0.y*wa.x + a0.z*wb.x + a0.w*wc.x;
                acc0.y += a0.x*w0.y + a0.y*wa.y + a0.z*wb.y + a0.w*wc.y;
                acc0.z += a0.x*w0.z + a0.y*wa.z + a0.z*wb.z + a0.w*wc.z;
                acc0.w += a0.x*w0.w + a0.y*wa.w + a0.z*wb.w + a0.w*wc.w;
                acc1.x += a1.x*w0.x + a1.y*wa.x + a1.z*wb.x + a1.w*wc.x;
                acc1.y += a1.x*w0.y + a1.y*wa.y + a1.z*wb.y + a1.w*wc.y;
                acc1.z += a1.x*w0.z + a1.y*wa.z + a1.z*wb.z + a1.w*wc.z;
                acc1.w += a1.x*w0.w + a1.y*wa.w + a1.z*wb.w + a1.w*wc.w;
            }
        }
    }
    const int pix0 = (bh + row)*W + (bw + col0);
    reinterpret_cast<float4*>(g_c1p + (size_t)zic*C1Q + (size_t)pix0*C1OC)[o4] = acc0;
    reinterpret_cast<float4*>(g_c1p + (size_t)zic*C1Q + (size_t)(pix0+1)*C1OC)[o4] = acc1;
}

// ---------------------------------------------------------------------------
// c1red: sum 8 ic-eighth partials -> g_c1. 32768 float4s.
// ---------------------------------------------------------------------------
__global__ __launch_bounds__(256) void c1red_kernel()
{
    int i = blockIdx.x * 256 + threadIdx.x;   // f4 index, 32768 total
    float4 s = make_float4(0.f,0.f,0.f,0.f);
    #pragma unroll
    for (int z = 0; z < 8; z++) {
        float4 v = reinterpret_cast<const float4*>(g_c1p + (size_t)z*C1Q)[i];
        s.x += v.x; s.y += v.y; s.z += v.z; s.w += v.w;
    }
    reinterpret_cast<float4*>(g_c1)[i] = s;
}

// ---------------------------------------------------------------------------
// conv2: VALID 3x3, 32 -> 64 ch, output 62x62. Tile 4x8 px; grid (8,16,2);
// z = oc half (32 oc). 128 threads, same shape as conv1.
// ---------------------------------------------------------------------------
__global__ __launch_bounds__(128) void conv2_kernel(
    const float* __restrict__ w2)
{
    __shared__ float sa[60*C1PITCH];     // 6x10 px halo x 32 ic
    const int bw = blockIdx.x * 8;
    const int bh = blockIdx.y * 4;
    const int zoc = blockIdx.z;          // oc half
    const int t = threadIdx.x;

    for (int idx = t; idx < 60*8; idx += 128) {
        int p = idx >> 3;
        int q = idx & 7;
        int r = p / 10, c = p % 10;
        int h = bh + r, w = bw + c;
        float4 v = make_float4(0.f,0.f,0.f,0.f);
        if (h < H && w < W)
            v = reinterpret_cast<const float4*>(g_c1 + (h*W + w)*C1OC)[q];
        reinterpret_cast<float4*>(sa + p*C1PITCH)[q] = v;
    }
    __syncthreads();

    const int o4   = t & 7;              // oc quad within half
    const int pp   = t >> 3;
    const int row  = pp >> 2;
    const int col0 = (pp & 3) * 2;
    float4 acc0 = make_float4(0.f,0.f,0.f,0.f);
    float4 acc1 = make_float4(0.f,0.f,0.f,0.f);

    #pragma unroll
    for (int kh = 0; kh < 3; kh++) {
        #pragma unroll
        for (int kw = 0; kw < 3; kw++) {
            const float* __restrict__ wp =
                w2 + ((size_t)((kh*3 + kw)*32))*64 + zoc*32 + o4*4;
            const float* __restrict__ ap0 =
                sa + ((row+kh)*10 + (col0+kw))*C1PITCH;
            const float* __restrict__ ap1 = ap0 + C1PITCH;
            #pragma unroll
            for (int ic4 = 0; ic4 < 8; ic4++) {
                float4 a0 = *reinterpret_cast<const float4*>(ap0 + ic4*4);
                float4 a1 = *reinterpret_cast<const float4*>(ap1 + ic4*4);
                float4 w0 = __ldg(reinterpret_cast<const float4*>(wp + (4*ic4+0)*64));
                float4 wa = __ldg(reinterpret_cast<const float4*>(wp + (4*ic4+1)*64));
                float4 wb = __ldg(reinterpret_cast<const float4*>(wp + (4*ic4+2)*64));
                float4 wc = __ldg(reinterpret_cast<const float4*>(wp + (4*ic4+3)*64));
                acc0.x += a0.x*w0.x + a0.y*wa.x + a0.z*wb.x + a0.w*wc.x;
                acc0.y += a0.x*w0.y + a0.y*wa.y + a0.z*wb.y + a0.w*wc.y;
                acc0.z += a0.x*w0.z + a0.y*wa.z + a0.z*wb.z + a0.w*wc.z;
                acc0.w += a0.x*w0.w + a0.y*wa.w + a0.z*wb.w + a0.w*wc.w;
                acc1.x += a1.x*w0.x + a1.y*wa.x + a1.z*wb.x + a1.w*wc.x;
                acc1.y += a1.x*w0.y + a1.y*wa.y + a1.z*wb.y + a1.w*wc.y;
                acc1.z += a1.x*w0.z + a1.y*wa.z + a1.z*wb.z + a1.w*wc.z;
                acc1.w += a1.x*w0.w + a1.y*wa.w + a1.z*wb.w + a1.w*wc.w;
            }
        }
    }
    const int h2  = bh + row;
    const int oc0 = zoc*32 + o4*4;
    if (h2 < H2) {
        #pragma unroll
        for (int s = 0; s < 2; s++) {
            int w2i = bw + col0 + s;
            if (w2i < H2) {
                float4 a = s ? acc1 : acc0;
                g_c2[(size_t)(oc0+0)*(H2*H2) + h2*H2 + w2i] = a.x;
                g_c2[(size_t)(oc0+1)*(H2*H2) + h2*H2 + w2i] = a.y;
                g_c2[(size_t)(oc0+2)*(H2*H2) + h2*H2 + w2i] = a.z;
                g_c2[(size_t)(oc0+3)*(H2*H2) + h2*H2 + w2i] = a.w;
            }
        }
    }
}

// ---------------------------------------------------------------------------
// 2x2 sum pool (stride 1) * 0.25 -> flat
// ---------------------------------------------------------------------------
__global__ __launch_bounds__(256) void pool_kernel()
{
    int idx = blockIdx.x * 256 + threadIdx.x;
    if (idx >= FLAT) return;
    int oc = idx / (HP*HP);
    int r = idx - oc*(HP*HP);
    int h = r / HP;
    int w = r - h*HP;
    const float* base = g_c2 + oc*(H2*H2) + h*H2 + w;
    g_flat[idx] = 0.25f * (base[0] + base[1] + base[H2] + base[H2+1]);
}

// ---------------------------------------------------------------------------
// dense1: flat(1x238144) @ W1(238144x128). Per-lane float4 loads, 4-row unroll.
// ---------------------------------------------------------------------------
__global__ __launch_bounds__(256) void dense1_kernel(const float* __restrict__ W1)
{
    const int t = threadIdx.x;
    const int lane = t & 31;
    const int wid  = t >> 5;
    const int row0 = blockIdx.x * D1ROWS;
    int lim = row0 + D1ROWS;
    if (lim > FLAT) lim = FLAT;

    float4 acc = make_float4(0.f,0.f,0.f,0.f);
    for (int k = 0; k < 104; k += 4) {          // 104*8 = 832 >= 805 rows
        #pragma unroll
        for (int u = 0; u < 4; u++) {
            int i = row0 + wid + 8*(k + u);
            if (i < lim) {
                float f = __ldg(g_flat + i);
                float4 wv = __ldg(reinterpret_cast<const float4*>(W1 + (size_t)i*128) + lane);
                acc.x += f*wv.x; acc.y += f*wv.y; acc.z += f*wv.z; acc.w += f*wv.w;
            }
        }
    }
    __shared__ float4 sred[256];
    sred[wid*32 + lane] = acc;
    __syncthreads();
    if (t < 32) {
        float4 s = sred[t];
        #pragma unroll
        for (int w = 1; w < 8; w++) {
            float4 v = sred[w*32 + t];
            s.x += v.x; s.y += v.y; s.z += v.z; s.w += v.w;
        }
        reinterpret_cast<float4*>(g_part1 + blockIdx.x*128)[t] = s;
    }
}

// ---------------------------------------------------------------------------
// fuse1: reduce r128; r_t = r128@W2; q_t = [in,r_t]@ctx; s_t = in@rec[:128]
// ---------------------------------------------------------------------------
__global__ __launch_bounds__(256) void fuse1_kernel(
    const float* __restrict__ inputs, const float* __restrict__ W2,
    const float* __restrict__ ctx, const float* __restrict__ rec)
{
    __shared__ float s_r128[128];
    __shared__ float s_rt[256];
    __shared__ float s_in[128];
    const int t = threadIdx.x;

    if (t < 128) {
        float a = 0.f;
        #pragma unroll 8
        for (int b = 0; b < D1BLK; b++) a += g_part1[b*128 + t];
        s_r128[t] = a;
        s_in[t] = inputs[t];
    }
    __syncthreads();

    float rt = 0.f;
    #pragma unroll 8
    for (int k = 0; k < 128; k++) rt += s_r128[k] * W2[k*256 + t];
    s_rt[t] = rt;
    g_rt[t] = rt;
    __syncthreads();

    float q = 0.f, sv = 0.f;
    #pragma unroll 8
    for (int k = 0; k < 128; k++) {
        float iv = s_in[k];
        q  += iv * ctx[k*256 + t];
        sv += iv * rec[k*256 + t];
    }
    #pragma unroll 8
    for (int k = 0; k < 256; k++)
        q += s_rt[k] * ctx[(128 + k)*256 + t];
    g_qt[t] = q;
    g_st[t] = sv;
}

// ---------------------------------------------------------------------------
// scores[p] = dot(q_t, memory[p,:])  — warp per row
// ---------------------------------------------------------------------------
__global__ __launch_bounds__(256) void scores_kernel(const float* __restrict__ mem)
{
    __shared__ float4 sq[64];
    const int t = threadIdx.x;
    if (t < 64) sq[t] = reinterpret_cast<const float4*>(g_qt)[t];
    __syncthreads();

    const int lane = t & 31;
    const int p = blockIdx.x * 8 + (t >> 5);
    const float4* mp = reinterpret_cast<const float4*>(mem + p*UNITS);
    float4 m0 = mp[lane];
    float4 m1 = mp[lane + 32];
    float4 q0 = sq[lane];
    float4 q1 = sq[lane + 32];
    float acc = m0.x*q0.x + m0.y*q0.y + m0.z*q0.z + m0.w*q0.w
              + m1.x*q1.x + m1.y*q1.y + m1.z*q1.z + m1.w*q1.w;
    #pragma unroll
    for (int o = 16; o > 0; o >>= 1)
        acc += __shfl_down_sync(0xffffffffu, acc, o);
    if (lane == 0) g_scores[p] = acc;
}

// ---------------------------------------------------------------------------
// softmax over 4096 scores (single block)
// ---------------------------------------------------------------------------
__global__ __launch_bounds__(1024) void softmax_kernel()
{
    __shared__ float red[32];
    const int t = threadIdx.x;
    float4 v = reinterpret_cast<const float4*>(g_scores)[t];
    float m = fmaxf(fmaxf(v.x, v.y), fmaxf(v.z, v.w));
    #pragma unroll
    for (int o = 16; o > 0; o >>= 1)
        m = fmaxf(m, __shfl_xor_sync(0xffffffffu, m, o));
    if ((t & 31) == 0) red[t >> 5] = m;
    __syncthreads();
    if (t < 32) {
        float mm = red[t];
        #pragma unroll
        for (int o = 16; o > 0; o >>= 1)
            mm = fmaxf(mm, __shfl_xor_sync(0xffffffffu, mm, o));
        red[t] = mm;
    }
    __syncthreads();
    const float gmax = red[0];
    __syncthreads();

    float4 e;
    e.x = expf(v.x - gmax); e.y = expf(v.y - gmax);
    e.z = expf(v.z - gmax); e.w = expf(v.w - gmax);
    reinterpret_cast<float4*>(g_expv)[t] = e;
    float s = e.x + e.y + e.z + e.w;
    #pragma unroll
    for (int o = 16; o > 0; o >>= 1)
        s += __shfl_xor_sync(0xffffffffu, s, o);
    if ((t & 31) == 0) red[t >> 5] = s;
    __syncthreads();
    if (t == 0) {
        float ss = 0.f;
        for (int i = 0; i < 32; i++) ss += red[i];
        g_invsum = 1.f / ss;
    }
}

// ---------------------------------------------------------------------------
// c_t partials: sum_p expv[p] * memory[p,:], 64 blocks of 64 rows
// ---------------------------------------------------------------------------
__global__ __launch_bounds__(256) void ctpart_kernel(const float* __restrict__ mem)
{
    const int c = threadIdx.x;
    const int base = blockIdx.x * 64;
    float acc = 0.f;
    #pragma unroll 4
    for (int p = base; p < base + 64; p++)
        acc += g_expv[p] * __ldg(mem + p*UNITS + c);
    g_partC[blockIdx.x*256 + c] = acc;
}

// ---------------------------------------------------------------------------
// Transpose memory (4096,256) -> new_mem region of out (split launches)
// ---------------------------------------------------------------------------
__global__ __launch_bounds__(256) void transpose_kernel(
    const float* __restrict__ mem, float* __restrict__ out, int yoff)
{
    __shared__ float tile[32][33];
    const int p0 = blockIdx.x * 32;
    const int c0 = (blockIdx.y + yoff) * 32;
    const int tx = threadIdx.x, ty = threadIdx.y;
    #pragma unroll
    for (int j = ty; j < 32; j += 8)
        tile[j][tx] = mem[(p0 + j)*UNITS + c0 + tx];
    __syncthreads();
    #pragma unroll
    for (int j = ty; j < 32; j += 8)
        out[512 + (size_t)(c0 + j)*NPIX + p0 + tx] = tile[tx][j];
}

// ---------------------------------------------------------------------------
// Final: reduce c_t, importances, mem update at (x,y); write c_t, r_t
// ---------------------------------------------------------------------------
__global__ __launch_bounds__(256) void final_kernel(
    const float* __restrict__ mem, const float* __restrict__ rec,
    const int* __restrict__ px, const int* __restrict__ py,
    float* __restrict__ out)
{
    __shared__ float s_st[256], s_mold[256];
    __shared__ float red[16];
    __shared__ float s_frac;
    const int c = threadIdx.x;
    const int pos = px[0]*W + py[0];

    float ct = 0.f;
    #pragma unroll 8
    for (int b = 0; b < CTBLK; b++) ct += g_partC[b*256 + c];
    ct *= g_invsum;
    float rt = g_rt[c];
    float st = g_st[c];
    s_st[c] = st;
    s_mold[c] = mem[pos*UNITS + c];
    out[c] = ct;
    out[256 + c] = rt;

    float li = st * ct;
    float gi = st * rt;
    #pragma unroll
    for (int o = 16; o > 0; o >>= 1) {
        li += __shfl_xor_sync(0xffffffffu, li, o);
        gi += __shfl_xor_sync(0xffffffffu, gi, o);
    }
    if ((c & 31) == 0) {
        red[c >> 5] = li;
        red[8 + (c >> 5)] = gi;
    }
    __syncthreads();
    if (c == 0) {
        float L = 0.f, G = 0.f;
        for (int i = 0; i < 8; i++) { L += red[i]; G += red[8 + i]; }
        s_frac = L / (L + G);
    }
    __syncthreads();

    const float frac = s_frac;
    float d = 0.f;
    #pragma unroll 8
    for (int k = 0; k < 256; k++)
        d += (s_mold[k] - s_st[k]) * __ldg(rec + (128 + k)*256 + c);
    out[512 + (size_t)c*NPIX + pos] = s_mold[c] + frac * d;
}

// ---------------------------------------------------------------------------
extern "C" void kernel_launch(void* const* d_in, const int* in_sizes, int n_in,
                              void* d_out, int out_size)
{
    const float* inputs = (const float*)d_in[0];
    const float* mem    = (const float*)d_in[1];
    const float* ck1    = (const float*)d_in[2];
    const float* ck2    = (const float*)d_in[3];
    const float* cd1    = (const float*)d_in[4];
    const float* cd2    = (const float*)d_in[5];
    const float* ctx    = (const float*)d_in[6];
    const float* rec    = (const float*)d_in[7];
    const int*   px     = (const int*)d_in[8];
    const int*   py     = (const int*)d_in[9];
    float* out = (float*)d_out;

    // Order chosen so conv2 is the 4th launch (profiled this round).
    transpose_kernel<<<dim3(NPIX / 32, 3), dim3(32, 8)>>>(mem, out, 0);
    conv1_kernel<<<dim3(8, 16, 8), 128>>>(mem, ck1);
    c1red_kernel<<<128, 256>>>();
    conv2_kernel<<<dim3(8, 16, 2), 128>>>(ck2);
    transpose_kernel<<<dim3(NPIX / 32, 3), dim3(32, 8)>>>(mem, out, 3);
    transpose_kernel<<<dim3(NPIX / 32, 2), dim3(32, 8)>>>(mem, out, 6);
    pool_kernel<<<(FLAT + 255) / 256, 256>>>();
    dense1_kernel<<<D1BLK, 256>>>(cd1);
    fuse1_kernel<<<1, 256>>>(inputs, cd2, ctx, rec);
    scores_kernel<<<NPIX / 8, 256>>>(mem);
    softmax_kernel<<<1, 1024>>>();
    ctpart_kernel<<<CTBLK, 256>>>(mem);
    final_kernel<<<1, 256>>>(mem, rec, px, py, out);
}